// round 8
// baseline (speedup 1.0000x reference)
#include <cuda_runtime.h>
#include <cuda_fp16.h>
#include <cstdint>

#define EPSF 1e-8f
#define COLS 8192
#define BS 64
#define NB 128          // quant-blocks per row
#define NCELL 256       // LUT cells over x_norm in [-1,1)
#define NTHREADS 256
#define MAGIC15 12582912.0f   // 1.5*2^23: keeps result in [2^23,2^24) binade
#define MBIAS 0x400000        // mantissa of MAGIC15

typedef unsigned int u32;

// One CTA per row (8192 floats), 256 threads, 32 elems/thread.
// R8 remap: 4 lanes per quant-block (thread owns 16 CONTIGUOUS elems of one
// block) -> block min/max needs only a 2-level 4-lane butterfly: 8 SHFLs per
// thread total (vs 64 in R4). Per load/store j, the warp's 32 lanes cover one
// contiguous 512B span (perfect coalescing).
// Keeps R7's exact magic-add (FADD-based round-to-nearest, no F2I) and the
// 8B LUT; drops R7's fkey/REDUX (measured ALU regression).
__global__ __launch_bounds__(NTHREADS, 4)
void nf4_kernel(const float* __restrict__ x, float* __restrict__ out)
{
    __shared__ float2 lut[NCELL + 1];   // {midpoint_cell, bits(half2(t_lo,t_hi))}
    __shared__ float2 qc[NB];           // {a, b} per quant-block
    __shared__ float scale_s[NB];
    __shared__ float bmin_s[NB];
    __shared__ float t_s[16];
    __shared__ float m_s[15];           // midpoints, in cell coordinates
    __shared__ float sm_smin, sm_smax;

    const int tid  = threadIdx.x;
    const int lane = tid & 31;
    const int warp = tid >> 5;
    const int g    = lane >> 2;         // 4-lane group id within warp (0..7)
    const int k    = lane & 3;          // sub-lane within group
    const long long row_base = (long long)blockIdx.x * COLS;

    // ---- phase 0: NF4 table (ndtri at midpoints, normalized, fp16-rounded) ----
    if (tid < 16) {
        // ndtri(p) = sqrt(2)*erfinv(2p-1); sqrt(2) cancels in max-abs norm.
        float p   = (2.0f * ((float)tid + 0.5f)) / 16.0f - 1.0f;
        float q   = erfinvf(p);
        float q0  = erfinvf(2.0f * 0.5f  / 16.0f - 1.0f);
        float q15 = erfinvf(2.0f * 15.5f / 16.0f - 1.0f);
        float qmax = fmaxf(fabsf(q0), fabsf(q15));
        t_s[tid] = __half2float(__float2half(q / qmax));
    }
    __syncthreads();
    if (tid < 15) {
        // boundary between level tid and tid+1 in cell coords:
        // cell(x_norm) = (x_norm + 1) * 128
        m_s[tid] = ((t_s[tid] + t_s[tid + 1]) * 0.5f + 1.0f) * 128.0f;
    }
    __syncthreads();

    // ---- phase 0b: range LUT, cell c covers fcell in [c-0.5, c+0.5)
    // (round-to-nearest indexing). Min midpoint gap ~10.8 cells -> each cell
    // straddles at most one boundary. Strict '>' matches argmin's
    // first-index tie rule (tie -> lower level).
    for (int c = tid; c <= NCELL; c += NTHREADS) {
        int jlo = 0, jhi = 0;
        float fc = (float)c;
        #pragma unroll
        for (int kk = 0; kk < 15; kk++) {
            jlo += (m_s[kk] < fc - 0.5f) ? 1 : 0;
            jhi += (m_s[kk] < fc + 0.5f) ? 1 : 0;
        }
        float2 e;
        __half2 tp;
        if (jhi > jlo) { e.x = m_s[jlo]; tp = __halves2half2(__float2half(t_s[jlo]), __float2half(t_s[jlo + 1])); }
        else           { e.x = -1e30f;   tp = __halves2half2(__float2half(t_s[jlo]), __float2half(t_s[jlo]));     }
        e.y = __uint_as_float(*reinterpret_cast<u32*>(&tp));
        lut[c] = e;
    }
    __syncthreads();   // LUT ready before phase-1 quantize

    // ---- phase 1: two macro-chunks of 16 contiguous elems per thread ----
    u32 stash[16];                      // 2 chunks x 8 packed half2
    #pragma unroll
    for (int m = 0; m < 2; m++) {
        const int qb    = warp * 16 + m * 8 + g;      // this thread's block
        const int ebase = qb * BS + k * 16;           // 16 contiguous elems
        float vr[16];
        #pragma unroll
        for (int j = 0; j < 4; j++)
            *reinterpret_cast<float4*>(vr + 4 * j) =
                *reinterpret_cast<const float4*>(x + row_base + ebase + 4 * j);

        // in-register reduce of 16 elems (tree, no MIO)
        float mn = vr[0], mx = vr[0];
        #pragma unroll
        for (int j = 1; j < 16; j++) {
            mn = fminf(mn, vr[j]);
            mx = fmaxf(mx, vr[j]);
        }
        // finish across the 4-lane group: 2 butterfly levels
        mn = fminf(mn, __shfl_xor_sync(0xffffffffu, mn, 1));
        mx = fmaxf(mx, __shfl_xor_sync(0xffffffffu, mx, 1));
        mn = fminf(mn, __shfl_xor_sync(0xffffffffu, mn, 2));
        mx = fmaxf(mx, __shfl_xor_sync(0xffffffffu, mx, 2));

        float scale = mx - mn;          // exact fp32 subtract, as reference
        if (k == 0) { bmin_s[qb] = mn; scale_s[qb] = scale; }

        // cell(x) = 256*(x - mn)/(scale + eps) = x*s1 + s2
        float s1 = __fdividef(256.0f, scale + EPSF);   // MUFU.RCP + FMUL
        float s2 = -mn * s1;
        #pragma unroll
        for (int j = 0; j < 16; j++) {
            float fcell = fmaf(vr[j], s1, s2);   // unrounded (compare value)
            float fbig  = fcell + MAGIC15;       // FADD: RNE(fcell) in mantissa
            int ic = (int)(__float_as_uint(fbig) & 0x7FFFFFu) - MBIAS;
            ic = max(0, min(NCELL, ic));         // safety clamp
            float2 L = lut[ic];
            u32 h2 = __float_as_uint(L.y);
            u32 t16 = (fcell > L.x) ? (h2 >> 16) : (h2 & 0xffffu);
            if ((j & 1) == 0) stash[m * 8 + (j >> 1)]  = t16;
            else              stash[m * 8 + (j >> 1)] |= t16 << 16;
        }
    }
    __syncthreads();

    // ---- phase 2: row-level min/max of the 128 block scales ----
    if (warp == 0) {
        float a0 = scale_s[lane];
        float a1 = scale_s[lane + 32];
        float a2 = scale_s[lane + 64];
        float a3 = scale_s[lane + 96];
        float mn = fminf(fminf(a0, a1), fminf(a2, a3));
        float mx = fmaxf(fmaxf(a0, a1), fmaxf(a2, a3));
        #pragma unroll
        for (int o = 16; o >= 1; o >>= 1) {
            mn = fminf(mn, __shfl_xor_sync(0xffffffffu, mn, o));
            mx = fmaxf(mx, __shfl_xor_sync(0xffffffffu, mx, o));
        }
        if (lane == 0) { sm_smin = mn; sm_smax = mx; }
    }
    __syncthreads();

    // ---- phase 3: per-block output constants ----
    if (tid < NB) {
        float smin  = sm_smin, smax = sm_smax;
        float scale = scale_s[tid];
        float bmin  = bmin_s[tid];
        float d     = smax - smin;
        // double quantization of scale (8-bit, round-half-even = rintf)
        float sq    = rintf((scale - smin) / (d + EPSF) * 255.0f);
        float srec  = smin + sq / 255.0f * d;
        // out = (t+1)/2 * srec + bmin == t*a + b
        float a = srec * 0.5f;
        float b = a + bmin;
        qc[tid] = make_float2(a, b);
    }
    __syncthreads();

    // ---- phase 4: dequant from register stash, coalesced store ----
    #pragma unroll
    for (int m = 0; m < 2; m++) {
        const int qb    = warp * 16 + m * 8 + g;
        const int ebase = qb * BS + k * 16;
        float2 ab = qc[qb];
        #pragma unroll
        for (int j = 0; j < 4; j++) {
            u32 wlo = stash[m * 8 + 2 * j];
            u32 whi = stash[m * 8 + 2 * j + 1];
            __half2 hlo = *reinterpret_cast<__half2*>(&wlo);
            __half2 hhi = *reinterpret_cast<__half2*>(&whi);
            float4 o;
            o.x = fmaf(__low2float(hlo),  ab.x, ab.y);
            o.y = fmaf(__high2float(hlo), ab.x, ab.y);
            o.z = fmaf(__low2float(hhi),  ab.x, ab.y);
            o.w = fmaf(__high2float(hhi), ab.x, ab.y);
            *reinterpret_cast<float4*>(out + row_base + ebase + 4 * j) = o;
        }
    }
}

extern "C" void kernel_launch(void* const* d_in, const int* in_sizes, int n_in,
                              void* d_out, int out_size)
{
    const float* x = (const float*)d_in[0];
    float* out = (float*)d_out;
    int rows = in_sizes[0] / COLS;   // 2048
    nf4_kernel<<<rows, NTHREADS>>>(x, out);
}

// round 9
// speedup vs baseline: 1.0069x; 1.0069x over previous
#include <cuda_runtime.h>
#include <cuda_fp16.h>
#include <cstdint>

#define EPSF 1e-8f
#define COLS 8192
#define BS 64
#define NB 128          // quant-blocks per row
#define NCELL 256       // LUT cells over x_norm in [-1,1)
#define NTHREADS 256

typedef unsigned int u32;

// monotone float<->u32 order-preserving keys (only applied to per-thread
// REDUCED values, 2 per iteration -- not per element)
__device__ __forceinline__ u32 fkey(float f) {
    u32 b = __float_as_uint(f);
    return b ^ ((u32)((int)b >> 31) | 0x80000000u);
}
__device__ __forceinline__ float unkey(u32 k) {
    u32 m = (~(u32)((int)k >> 31)) | 0x80000000u;
    return __uint_as_float(k ^ m);
}

// One CTA per row (8192 floats). Warp w owns quant-blocks [16w, 16w+16).
// Iteration i: lanes 0-15 cover block 16w+2i, lanes 16-31 cover 16w+2i+1
// (float4 per lane; each warp-iter touches 512 contiguous bytes, coalesced).
//
// R9 = R4 (best measured structure: 8 independent iterations, F2I indexing)
// with ONE delta: the 16-lane min/max butterfly (8 SHFL + 8 FMNMX, ~120cyc
// serial) is replaced by __reduce_{min,max}_sync on key-encoded reduced
// values (2 REDUX + 12 ALU, ~35cyc serial). MIO ops -6/iter.
__global__ __launch_bounds__(NTHREADS, 4)
void nf4_kernel(const float* __restrict__ x, float* __restrict__ out)
{
    __shared__ float2 lut[NCELL + 1];   // {midpoint_cell, bits(half2(t_lo,t_hi))}
    __shared__ float2 qc[NB];           // {a, b} per quant-block
    __shared__ float scale_s[NB];
    __shared__ float bmin_s[NB];
    __shared__ float t_s[16];
    __shared__ float m_s[15];           // midpoints, in cell coordinates
    __shared__ float sm_smin, sm_smax;

    const int tid  = threadIdx.x;
    const int lane = tid & 31;
    const int warp = tid >> 5;
    const long long row_base = (long long)blockIdx.x * COLS;
    const u32 hmask = (lane < 16) ? 0x0000FFFFu : 0xFFFF0000u;

    // ---- phase 0: NF4 table (ndtri at midpoints, normalized, fp16-rounded) ----
    if (tid < 16) {
        // ndtri(p) = sqrt(2)*erfinv(2p-1); sqrt(2) cancels in max-abs norm.
        float p   = (2.0f * ((float)tid + 0.5f)) / 16.0f - 1.0f;
        float q   = erfinvf(p);
        float q0  = erfinvf(2.0f * 0.5f  / 16.0f - 1.0f);
        float q15 = erfinvf(2.0f * 15.5f / 16.0f - 1.0f);
        float qmax = fmaxf(fabsf(q0), fabsf(q15));
        t_s[tid] = __half2float(__float2half(q / qmax));
    }
    __syncthreads();
    if (tid < 15) {
        // boundary between level tid and tid+1 in cell coords:
        // cell(x_norm) = (x_norm + 1) * 128
        m_s[tid] = ((t_s[tid] + t_s[tid + 1]) * 0.5f + 1.0f) * 128.0f;
    }
    __syncthreads();

    // ---- phase 0b: range LUT, cell c covers fcell in [c, c+1) (truncation
    // indexing). Min midpoint gap ~10.8 cells -> each cell straddles at most
    // one boundary. Strict '>' matches argmin's first-index tie rule.
    for (int c = tid; c <= NCELL; c += NTHREADS) {
        int jlo = 0, jhi = 0;
        float fc = (float)c;
        #pragma unroll
        for (int kk = 0; kk < 15; kk++) {
            jlo += (m_s[kk] < fc)        ? 1 : 0;
            jhi += (m_s[kk] < fc + 1.0f) ? 1 : 0;
        }
        float2 e;
        __half2 tp;
        if (jhi > jlo) { e.x = m_s[jlo]; tp = __halves2half2(__float2half(t_s[jlo]), __float2half(t_s[jlo + 1])); }
        else           { e.x = -1e30f;   tp = __halves2half2(__float2half(t_s[jlo]), __float2half(t_s[jlo]));     }
        e.y = __uint_as_float(*reinterpret_cast<u32*>(&tp));
        lut[c] = e;
    }
    __syncthreads();   // LUT ready before phase-1 quantize

    // ---- phase 1: single pass: load, block min/max, quantize, stash fp16 ----
    const int qb_base = warp * 16;
    u32 stash[16];                      // 8 iters x 2 packed half2
    #pragma unroll
    for (int i = 0; i < 8; i++) {
        int e = (qb_base + 2 * i) * BS + lane * 4;
        float4 v = *reinterpret_cast<const float4*>(x + row_base + e);
        // 4-elem in-register tree reduce (float), then one 16-lane REDUX on
        // key-encoded values (2 MIO ops instead of an 8-SHFL butterfly)
        float mn4 = fminf(fminf(v.x, v.y), fminf(v.z, v.w));
        float mx4 = fmaxf(fmaxf(v.x, v.y), fmaxf(v.z, v.w));
        float mn = unkey(__reduce_min_sync(hmask, fkey(mn4)));
        float mx = unkey(__reduce_max_sync(hmask, fkey(mx4)));
        float scale = mx - mn;          // exact fp32 subtract, as reference
        if ((lane & 15) == 0) {
            int qb = qb_base + 2 * i + (lane >> 4);
            bmin_s[qb]  = mn;
            scale_s[qb] = scale;
        }
        // cell(x) = 256*(x - mn)/(scale + eps) = x*s1 + s2
        float s1 = __fdividef(256.0f, scale + EPSF);   // MUFU.RCP + FMUL
        float s2 = -mn * s1;
        const float* vi = reinterpret_cast<const float*>(&v);
        u32 w01 = 0, w23 = 0;
        #pragma unroll
        for (int j = 0; j < 4; j++) {
            float fcell = fmaf(vi[j], s1, s2);
            int ic = (int)fcell;        // trunc clamps tiny negatives to 0
            float2 L = lut[ic];         // ic in [0,256] -> 257 entries
            u32 h2 = __float_as_uint(L.y);
            u32 t16 = (fcell > L.x) ? (h2 >> 16) : (h2 & 0xffffu);
            if (j == 0) w01  = t16;
            if (j == 1) w01 |= t16 << 16;
            if (j == 2) w23  = t16;
            if (j == 3) w23 |= t16 << 16;
        }
        stash[2 * i]     = w01;
        stash[2 * i + 1] = w23;
    }
    __syncthreads();

    // ---- phase 2: row-level min/max of the 128 block scales ----
    if (warp == 0) {
        float a0 = scale_s[lane];
        float a1 = scale_s[lane + 32];
        float a2 = scale_s[lane + 64];
        float a3 = scale_s[lane + 96];
        float mn4 = fminf(fminf(a0, a1), fminf(a2, a3));
        float mx4 = fmaxf(fmaxf(a0, a1), fmaxf(a2, a3));
        float mn = unkey(__reduce_min_sync(0xFFFFFFFFu, fkey(mn4)));
        float mx = unkey(__reduce_max_sync(0xFFFFFFFFu, fkey(mx4)));
        if (lane == 0) { sm_smin = mn; sm_smax = mx; }
    }
    __syncthreads();

    // ---- phase 3: per-block output constants ----
    if (tid < NB) {
        float smin  = sm_smin, smax = sm_smax;
        float scale = scale_s[tid];
        float bmin  = bmin_s[tid];
        float d     = smax - smin;
        // double quantization of scale (8-bit, round-half-even = rintf)
        float sq    = rintf((scale - smin) / (d + EPSF) * 255.0f);
        float srec  = smin + sq / 255.0f * d;
        // out = (t+1)/2 * srec + bmin == t*a + b
        float a = srec * 0.5f;
        float b = a + bmin;
        qc[tid] = make_float2(a, b);
    }
    __syncthreads();

    // ---- phase 4: dequant from register stash, coalesced store ----
    #pragma unroll
    for (int i = 0; i < 8; i++) {
        int qb = qb_base + 2 * i + (lane >> 4);
        int e  = (qb_base + 2 * i) * BS + lane * 4;
        float2 ab = qc[qb];
        u32 w01 = stash[2 * i];
        u32 w23 = stash[2 * i + 1];
        __half2 h01 = *reinterpret_cast<__half2*>(&w01);
        __half2 h23 = *reinterpret_cast<__half2*>(&w23);
        float4 o;
        o.x = fmaf(__low2float(h01),  ab.x, ab.y);
        o.y = fmaf(__high2float(h01), ab.x, ab.y);
        o.z = fmaf(__low2float(h23),  ab.x, ab.y);
        o.w = fmaf(__high2float(h23), ab.x, ab.y);
        *reinterpret_cast<float4*>(out + row_base + e) = o;
    }
}

extern "C" void kernel_launch(void* const* d_in, const int* in_sizes, int n_in,
                              void* d_out, int out_size)
{
    const float* x = (const float*)d_in[0];
    float* out = (float*)d_out;
    int rows = in_sizes[0] / COLS;   // 2048
    nf4_kernel<<<rows, NTHREADS>>>(x, out);
}

// round 10
// speedup vs baseline: 1.1952x; 1.1870x over previous
#include <cuda_runtime.h>
#include <cuda_fp16.h>
#include <cstdint>

#define EPSF 1e-8f
#define COLS 8192
#define BS 64
#define NB 128          // quant-blocks per row
#define NCELL 256       // LUT cells over x_norm in [-1,1)
#define NTHREADS 256

typedef unsigned int u32;

// One CTA per row (8192 floats). R10 mapping: 8 lanes per quant-block.
// Warp w, iteration i (0..3): group g = lane>>3 owns block qb = 16w + 4i + g.
// Thread k = lane&7 holds elems [k*4, k*4+4) and [32+k*4, 32+k*4+4) of its
// block (two float4s). Each warp-wide LDG covers 4 dense 128B segments.
// Block min/max: 8-elem in-register tree + 3-level 8-lane butterfly
// (3.25 ops/elem vs 5.5 in R4). Quantize path byte-identical to R4.
__global__ __launch_bounds__(NTHREADS, 4)
void nf4_kernel(const float* __restrict__ x, float* __restrict__ out)
{
    __shared__ float2 lut[NCELL + 1];   // {midpoint_cell, bits(half2(t_lo,t_hi))}
    __shared__ float2 qc[NB];           // {a, b} per quant-block
    __shared__ float scale_s[NB];
    __shared__ float bmin_s[NB];
    __shared__ float t_s[16];
    __shared__ float m_s[15];           // midpoints, in cell coordinates
    __shared__ float sm_smin, sm_smax;

    const int tid  = threadIdx.x;
    const int lane = tid & 31;
    const int warp = tid >> 5;
    const int g    = lane >> 3;         // 8-lane group (0..3)
    const int k    = lane & 7;          // sub-lane in group
    const long long row_base = (long long)blockIdx.x * COLS;

    // ---- phase 0: NF4 table (ndtri at midpoints, normalized, fp16-rounded) ----
    if (tid < 16) {
        // ndtri(p) = sqrt(2)*erfinv(2p-1); sqrt(2) cancels in max-abs norm.
        float p   = (2.0f * ((float)tid + 0.5f)) / 16.0f - 1.0f;
        float q   = erfinvf(p);
        float q0  = erfinvf(2.0f * 0.5f  / 16.0f - 1.0f);
        float q15 = erfinvf(2.0f * 15.5f / 16.0f - 1.0f);
        float qmax = fmaxf(fabsf(q0), fabsf(q15));
        t_s[tid] = __half2float(__float2half(q / qmax));
    }
    __syncthreads();
    if (tid < 15) {
        // boundary between level tid and tid+1 in cell coords:
        // cell(x_norm) = (x_norm + 1) * 128
        m_s[tid] = ((t_s[tid] + t_s[tid + 1]) * 0.5f + 1.0f) * 128.0f;
    }
    __syncthreads();

    // ---- phase 0b: range LUT, cell c covers fcell in [c, c+1) (truncation
    // indexing). Min midpoint gap ~10.8 cells -> each cell straddles at most
    // one boundary. Strict '>' matches argmin's first-index tie rule.
    for (int c = tid; c <= NCELL; c += NTHREADS) {
        int jlo = 0, jhi = 0;
        float fc = (float)c;
        #pragma unroll
        for (int kk = 0; kk < 15; kk++) {
            jlo += (m_s[kk] < fc)        ? 1 : 0;
            jhi += (m_s[kk] < fc + 1.0f) ? 1 : 0;
        }
        float2 e;
        __half2 tp;
        if (jhi > jlo) { e.x = m_s[jlo]; tp = __halves2half2(__float2half(t_s[jlo]), __float2half(t_s[jlo + 1])); }
        else           { e.x = -1e30f;   tp = __halves2half2(__float2half(t_s[jlo]), __float2half(t_s[jlo]));     }
        e.y = __uint_as_float(*reinterpret_cast<u32*>(&tp));
        lut[c] = e;
    }
    __syncthreads();   // LUT ready before phase-1 quantize

    // ---- phase 1: 4 iterations; each: one block per 8-lane group ----
    u32 stash[16];                      // 4 iters x 8 elems -> 4 packed half2
    #pragma unroll
    for (int i = 0; i < 4; i++) {
        const int qb    = warp * 16 + i * 4 + g;
        const int ebase = qb * BS + k * 4;
        float4 v0 = *reinterpret_cast<const float4*>(x + row_base + ebase);
        float4 v1 = *reinterpret_cast<const float4*>(x + row_base + ebase + 32);

        // 8-elem in-register tree
        float mn = fminf(fminf(fminf(v0.x, v0.y), fminf(v0.z, v0.w)),
                         fminf(fminf(v1.x, v1.y), fminf(v1.z, v1.w)));
        float mx = fmaxf(fmaxf(fmaxf(v0.x, v0.y), fmaxf(v0.z, v0.w)),
                         fmaxf(fmaxf(v1.x, v1.y), fmaxf(v1.z, v1.w)));
        // 3-level butterfly within the 8-lane group
        mn = fminf(mn, __shfl_xor_sync(0xffffffffu, mn, 1));
        mx = fmaxf(mx, __shfl_xor_sync(0xffffffffu, mx, 1));
        mn = fminf(mn, __shfl_xor_sync(0xffffffffu, mn, 2));
        mx = fmaxf(mx, __shfl_xor_sync(0xffffffffu, mx, 2));
        mn = fminf(mn, __shfl_xor_sync(0xffffffffu, mn, 4));
        mx = fmaxf(mx, __shfl_xor_sync(0xffffffffu, mx, 4));

        float scale = mx - mn;          // exact fp32 subtract, as reference
        if (k == 0) { bmin_s[qb] = mn; scale_s[qb] = scale; }

        // cell(x) = 256*(x - mn)/(scale + eps) = x*s1 + s2
        float s1 = __fdividef(256.0f, scale + EPSF);   // MUFU.RCP + FMUL
        float s2 = -mn * s1;
        float vr[8];
        *reinterpret_cast<float4*>(vr)     = v0;
        *reinterpret_cast<float4*>(vr + 4) = v1;
        #pragma unroll
        for (int j = 0; j < 8; j++) {
            float fcell = fmaf(vr[j], s1, s2);
            int ic = (int)fcell;        // trunc clamps tiny negatives to 0
            float2 L = lut[ic];         // ic in [0,256] -> 257 entries
            u32 h2 = __float_as_uint(L.y);
            u32 t16 = (fcell > L.x) ? (h2 >> 16) : (h2 & 0xffffu);
            if ((j & 1) == 0) stash[i * 4 + (j >> 1)]  = t16;
            else              stash[i * 4 + (j >> 1)] |= t16 << 16;
        }
    }
    __syncthreads();

    // ---- phase 2: row-level min/max of the 128 block scales ----
    if (warp == 0) {
        float a0 = scale_s[lane];
        float a1 = scale_s[lane + 32];
        float a2 = scale_s[lane + 64];
        float a3 = scale_s[lane + 96];
        float mn = fminf(fminf(a0, a1), fminf(a2, a3));
        float mx = fmaxf(fmaxf(a0, a1), fmaxf(a2, a3));
        #pragma unroll
        for (int o = 16; o >= 1; o >>= 1) {
            mn = fminf(mn, __shfl_xor_sync(0xffffffffu, mn, o));
            mx = fmaxf(mx, __shfl_xor_sync(0xffffffffu, mx, o));
        }
        if (lane == 0) { sm_smin = mn; sm_smax = mx; }
    }
    __syncthreads();

    // ---- phase 3: per-block output constants ----
    if (tid < NB) {
        float smin  = sm_smin, smax = sm_smax;
        float scale = scale_s[tid];
        float bmin  = bmin_s[tid];
        float d     = smax - smin;
        // double quantization of scale (8-bit, round-half-even = rintf)
        float sq    = rintf((scale - smin) / (d + EPSF) * 255.0f);
        float srec  = smin + sq / 255.0f * d;
        // out = (t+1)/2 * srec + bmin == t*a + b
        float a = srec * 0.5f;
        float b = a + bmin;
        qc[tid] = make_float2(a, b);
    }
    __syncthreads();

    // ---- phase 4: dequant from register stash, coalesced store ----
    #pragma unroll
    for (int i = 0; i < 4; i++) {
        const int qb    = warp * 16 + i * 4 + g;
        const int ebase = qb * BS + k * 4;
        float2 ab = qc[qb];
        u32 w0 = stash[i * 4 + 0];
        u32 w1 = stash[i * 4 + 1];
        u32 w2 = stash[i * 4 + 2];
        u32 w3 = stash[i * 4 + 3];
        __half2 h0 = *reinterpret_cast<__half2*>(&w0);
        __half2 h1 = *reinterpret_cast<__half2*>(&w1);
        __half2 h2 = *reinterpret_cast<__half2*>(&w2);
        __half2 h3 = *reinterpret_cast<__half2*>(&w3);
        float4 o0, o1;
        o0.x = fmaf(__low2float(h0),  ab.x, ab.y);
        o0.y = fmaf(__high2float(h0), ab.x, ab.y);
        o0.z = fmaf(__low2float(h1),  ab.x, ab.y);
        o0.w = fmaf(__high2float(h1), ab.x, ab.y);
        o1.x = fmaf(__low2float(h2),  ab.x, ab.y);
        o1.y = fmaf(__high2float(h2), ab.x, ab.y);
        o1.z = fmaf(__low2float(h3),  ab.x, ab.y);
        o1.w = fmaf(__high2float(h3), ab.x, ab.y);
        *reinterpret_cast<float4*>(out + row_base + ebase)      = o0;
        *reinterpret_cast<float4*>(out + row_base + ebase + 32) = o1;
    }
}

extern "C" void kernel_launch(void* const* d_in, const int* in_sizes, int n_in,
                              void* d_out, int out_size)
{
    const float* x = (const float*)d_in[0];
    float* out = (float*)d_out;
    int rows = in_sizes[0] / COLS;   // 2048
    nf4_kernel<<<rows, NTHREADS>>>(x, out);
}

// round 11
// speedup vs baseline: 1.2551x; 1.0500x over previous
#include <cuda_runtime.h>
#include <cuda_fp16.h>
#include <cstdint>

#define EPSF 1e-8f
#define COLS 8192
#define BS 64
#define NB 128          // quant-blocks per row
#define NCELL 512       // LUT cells over x_norm in [-1,1)
#define NTHREADS 256

typedef unsigned int u32;

// One CTA per row (8192 floats). Mapping (R10, proven): 8 lanes per block.
// Warp w, iter i (0..3): group g = lane>>3 owns block qb = 16w + 4i + g.
// Thread k = lane&7 holds elems [k*4,k*4+4) and [32+k*4,...) of its block.
//
// R11 deltas vs R10 (attack LDS-gather wavefronts, the largest MIO item):
//  - NCELL 256 -> 512; main LUT entry 4B: packed {t_hi_h16 | t_lo_h16}
//    (LDS.32 gather, ~half the bank footprint of the old LDS.64)
//  - fp32 midpoint in a SEPARATE LUT, gathered only when the cell straddles
//    a boundary (t_hi bits != t_lo bits): ~3% of elements -> ~1 lane/warp
//  - __ldcs / __stcs streaming hints (x read once, out written once)
__global__ __launch_bounds__(NTHREADS, 4)
void nf4_kernel(const float* __restrict__ x, float* __restrict__ out)
{
    __shared__ u32   lutv[NCELL + 1];   // packed {t_hi, t_lo} fp16 pair
    __shared__ float lutm[NCELL + 1];   // fp32 midpoint (straddle cells only)
    __shared__ float2 qc[NB];           // {a, b} per quant-block
    __shared__ float scale_s[NB];
    __shared__ float bmin_s[NB];
    __shared__ float t_s[16];
    __shared__ float m_s[15];           // midpoints, in 512-cell coordinates
    __shared__ float sm_smin, sm_smax;

    const int tid  = threadIdx.x;
    const int lane = tid & 31;
    const int warp = tid >> 5;
    const int g    = lane >> 3;         // 8-lane group (0..3)
    const int k    = lane & 7;          // sub-lane in group
    const long long row_base = (long long)blockIdx.x * COLS;

    // ---- phase 0: NF4 table (ndtri at midpoints, normalized, fp16-rounded) ----
    if (tid < 16) {
        // ndtri(p) = sqrt(2)*erfinv(2p-1); sqrt(2) cancels in max-abs norm.
        float p   = (2.0f * ((float)tid + 0.5f)) / 16.0f - 1.0f;
        float q   = erfinvf(p);
        float q0  = erfinvf(2.0f * 0.5f  / 16.0f - 1.0f);
        float q15 = erfinvf(2.0f * 15.5f / 16.0f - 1.0f);
        float qmax = fmaxf(fabsf(q0), fabsf(q15));
        t_s[tid] = __half2float(__float2half(q / qmax));
    }
    __syncthreads();
    if (tid < 15) {
        // boundary between level tid and tid+1 in 512-cell coords:
        // cell(x_norm) = (x_norm + 1) * 256
        m_s[tid] = ((t_s[tid] + t_s[tid + 1]) * 0.5f + 1.0f) * 256.0f;
    }
    __syncthreads();

    // ---- phase 0b: range LUT, cell c covers fcell in [c, c+1) (truncation
    // indexing). Min midpoint gap ~21.6 cells -> each cell straddles at most
    // one boundary. Strict '>' matches argmin's first-index tie rule.
    for (int c = tid; c <= NCELL; c += NTHREADS) {
        int jlo = 0, jhi = 0;
        float fc = (float)c;
        #pragma unroll
        for (int kk = 0; kk < 15; kk++) {
            jlo += (m_s[kk] < fc)        ? 1 : 0;
            jhi += (m_s[kk] < fc + 1.0f) ? 1 : 0;
        }
        u32 tlo = (u32)__half_as_ushort(__float2half(t_s[jlo]));
        u32 thi;
        float mid;
        if (jhi > jlo) { thi = (u32)__half_as_ushort(__float2half(t_s[jlo + 1])); mid = m_s[jlo]; }
        else           { thi = tlo;                                               mid = -1e30f;   }
        lutv[c] = (thi << 16) | tlo;
        lutm[c] = mid;
    }
    __syncthreads();   // LUT ready before phase-1 quantize

    // ---- phase 1: 4 iterations; each: one block per 8-lane group ----
    u32 stash[16];                      // 4 iters x 8 elems -> 4 packed half2
    #pragma unroll
    for (int i = 0; i < 4; i++) {
        const int qb    = warp * 16 + i * 4 + g;
        const int ebase = qb * BS + k * 4;
        float4 v0 = __ldcs(reinterpret_cast<const float4*>(x + row_base + ebase));
        float4 v1 = __ldcs(reinterpret_cast<const float4*>(x + row_base + ebase + 32));

        // 8-elem in-register tree
        float mn = fminf(fminf(fminf(v0.x, v0.y), fminf(v0.z, v0.w)),
                         fminf(fminf(v1.x, v1.y), fminf(v1.z, v1.w)));
        float mx = fmaxf(fmaxf(fmaxf(v0.x, v0.y), fmaxf(v0.z, v0.w)),
                         fmaxf(fmaxf(v1.x, v1.y), fmaxf(v1.z, v1.w)));
        // 3-level butterfly within the 8-lane group
        mn = fminf(mn, __shfl_xor_sync(0xffffffffu, mn, 1));
        mx = fmaxf(mx, __shfl_xor_sync(0xffffffffu, mx, 1));
        mn = fminf(mn, __shfl_xor_sync(0xffffffffu, mn, 2));
        mx = fmaxf(mx, __shfl_xor_sync(0xffffffffu, mx, 2));
        mn = fminf(mn, __shfl_xor_sync(0xffffffffu, mn, 4));
        mx = fmaxf(mx, __shfl_xor_sync(0xffffffffu, mx, 4));

        float scale = mx - mn;          // exact fp32 subtract, as reference
        if (k == 0) { bmin_s[qb] = mn; scale_s[qb] = scale; }

        // cell(x) = 512*(x - mn)/(scale + eps) = x*s1 + s2
        float s1 = __fdividef(512.0f, scale + EPSF);   // MUFU.RCP + FMUL
        float s2 = -mn * s1;
        float vr[8];
        *reinterpret_cast<float4*>(vr)     = v0;
        *reinterpret_cast<float4*>(vr + 4) = v1;
        #pragma unroll
        for (int j = 0; j < 8; j++) {
            float fcell = fmaf(vr[j], s1, s2);
            int ic = (int)fcell;        // trunc clamps tiny negatives to 0
            u32 tt  = lutv[ic];         // 4B gather
            u32 t16 = tt & 0xffffu;
            u32 thi = tt >> 16;
            if (thi != t16) {           // straddling cell: ~3% of elements
                if (fcell > lutm[ic]) t16 = thi;
            }
            if ((j & 1) == 0) stash[i * 4 + (j >> 1)]  = t16;
            else              stash[i * 4 + (j >> 1)] |= t16 << 16;
        }
    }
    __syncthreads();

    // ---- phase 2: row-level min/max of the 128 block scales ----
    if (warp == 0) {
        float a0 = scale_s[lane];
        float a1 = scale_s[lane + 32];
        float a2 = scale_s[lane + 64];
        float a3 = scale_s[lane + 96];
        float mn = fminf(fminf(a0, a1), fminf(a2, a3));
        float mx = fmaxf(fmaxf(a0, a1), fmaxf(a2, a3));
        #pragma unroll
        for (int o = 16; o >= 1; o >>= 1) {
            mn = fminf(mn, __shfl_xor_sync(0xffffffffu, mn, o));
            mx = fmaxf(mx, __shfl_xor_sync(0xffffffffu, mx, o));
        }
        if (lane == 0) { sm_smin = mn; sm_smax = mx; }
    }
    __syncthreads();

    // ---- phase 3: per-block output constants ----
    if (tid < NB) {
        float smin  = sm_smin, smax = sm_smax;
        float scale = scale_s[tid];
        float bmin  = bmin_s[tid];
        float d     = smax - smin;
        // double quantization of scale (8-bit, round-half-even = rintf)
        float sq    = rintf((scale - smin) / (d + EPSF) * 255.0f);
        float srec  = smin + sq / 255.0f * d;
        // out = (t+1)/2 * srec + bmin == t*a + b
        float a = srec * 0.5f;
        float b = a + bmin;
        qc[tid] = make_float2(a, b);
    }
    __syncthreads();

    // ---- phase 4: dequant from register stash, coalesced streaming store ----
    #pragma unroll
    for (int i = 0; i < 4; i++) {
        const int qb    = warp * 16 + i * 4 + g;
        const int ebase = qb * BS + k * 4;
        float2 ab = qc[qb];
        u32 w0 = stash[i * 4 + 0];
        u32 w1 = stash[i * 4 + 1];
        u32 w2 = stash[i * 4 + 2];
        u32 w3 = stash[i * 4 + 3];
        __half2 h0 = *reinterpret_cast<__half2*>(&w0);
        __half2 h1 = *reinterpret_cast<__half2*>(&w1);
        __half2 h2 = *reinterpret_cast<__half2*>(&w2);
        __half2 h3 = *reinterpret_cast<__half2*>(&w3);
        float4 o0, o1;
        o0.x = fmaf(__low2float(h0),  ab.x, ab.y);
        o0.y = fmaf(__high2float(h0), ab.x, ab.y);
        o0.z = fmaf(__low2float(h1),  ab.x, ab.y);
        o0.w = fmaf(__high2float(h1), ab.x, ab.y);
        o1.x = fmaf(__low2float(h2),  ab.x, ab.y);
        o1.y = fmaf(__high2float(h2), ab.x, ab.y);
        o1.z = fmaf(__low2float(h3),  ab.x, ab.y);
        o1.w = fmaf(__high2float(h3), ab.x, ab.y);
        __stcs(reinterpret_cast<float4*>(out + row_base + ebase),      o0);
        __stcs(reinterpret_cast<float4*>(out + row_base + ebase + 32), o1);
    }
}

extern "C" void kernel_launch(void* const* d_in, const int* in_sizes, int n_in,
                              void* d_out, int out_size)
{
    const float* x = (const float*)d_in[0];
    float* out = (float*)d_out;
    int rows = in_sizes[0] / COLS;   // 2048
    nf4_kernel<<<rows, NTHREADS>>>(x, out);
}